// round 2
// baseline (speedup 1.0000x reference)
#include <cuda_runtime.h>
#include <math.h>

#define TT 2048
#define BB 16
#define NN 2048
#define HH 1024
#define SPL 9
#define CHUNK 228   // ceil(2048/9) -> splits 0..7: 228 t, split 8: 224 t (both %4==0)

// scratch (device globals: no allocation allowed in kernel_launch)
__device__ float g_decfea[BB*NN];
__device__ float g_scores[TT*BB];
__device__ float g_m[BB*SPL];
__device__ float g_z[BB*SPL];
__device__ float g_acc[BB*SPL*NN];
__device__ unsigned char g_mask8[TT*BB];

// accurate branch-free tanh: 2 MUFU (EX2 + RCP), ~few-ulp error
__device__ __forceinline__ float tanh_acc(float x){
    float ax = fabsf(x);
    float t  = __expf(-2.0f * ax);            // in (0,1]
    float r  = __fdividef(1.0f - t, 1.0f + t); // denom in [1,2] -> safe fast divide
    return copysignf(r, x);
}

// ---------------------------------------------------------------------------
// Kernel 0: normalize the padding mask to uint8 regardless of storage dtype.
// The reference produces a bool array; the harness may materialize it as
// int32 (0/1 words), float32 (0.0/1.0), or raw bytes. Detect from the first
// 32 words (random ~50% mask => misdetection prob ~2^-32) and convert.
// ---------------------------------------------------------------------------
__global__ void k_maskconv(const unsigned char* __restrict__ mraw){
    const unsigned int* w = (const unsigned int*)mraw;
    int is_word = 1;   // int32 or float32 storage (one element per 4-byte word)
    #pragma unroll
    for (int i = 0; i < 32; ++i){
        unsigned int x = w[i];
        if (x != 0u && x != 1u && x != 0x3F800000u) is_word = 0;
    }
    int idx = blockIdx.x*256 + threadIdx.x;
    if (idx < TT*BB){
        unsigned char mv = is_word ? (unsigned char)(w[idx] != 0u)
                                   : (unsigned char)(mraw[idx] != 0);
        g_mask8[idx] = mv;
    }
}

// ---------------------------------------------------------------------------
// Kernel 1: dec_fea[b,n] = dot(dec[b,:], Wd[n,:]) + bd[n]
// 128 blocks x 256 thr; each block owns 16 n-rows; dec kept in smem (8 b at a time).
// ---------------------------------------------------------------------------
__global__ void k_decfea(const float* __restrict__ dec,
                         const float* __restrict__ Wd,
                         const float* __restrict__ bd){
    __shared__ float sdec[8*HH];       // 32 KB
    __shared__ float sred[8][256];     // 8 KB
    int tid  = threadIdx.x;
    int wid  = tid >> 5, lane = tid & 31;
    int nbase = blockIdx.x * 16;
    for (int half = 0; half < 2; ++half){
        const float4* dg = (const float4*)(dec + half*8*HH);
        float4* sg = (float4*)sdec;
        #pragma unroll
        for (int i = 0; i < 8; ++i) sg[tid + i*256] = dg[tid + i*256];
        __syncthreads();
        for (int r = 0; r < 16; ++r){
            int n = nbase + r;
            float4 w = ((const float4*)(Wd + (size_t)n*HH))[tid];
            float a[8];
            #pragma unroll
            for (int b = 0; b < 8; ++b){
                float4 d = ((const float4*)(sdec + b*HH))[tid];
                a[b] = w.x*d.x + w.y*d.y + w.z*d.z + w.w*d.w;
            }
            #pragma unroll
            for (int b = 0; b < 8; ++b) sred[b][tid] = a[b];
            __syncthreads();
            // warp `wid` reduces accumulator b==wid
            float vsum = 0.f;
            #pragma unroll
            for (int k = 0; k < 8; ++k) vsum += sred[wid][lane + 32*k];
            #pragma unroll
            for (int off = 16; off; off >>= 1)
                vsum += __shfl_xor_sync(0xffffffffu, vsum, off);
            if (lane == 0) g_decfea[(half*8 + wid)*NN + n] = vsum + bd[n];
            __syncthreads();
        }
    }
}

// ---------------------------------------------------------------------------
// Kernel 2: fused scores + online softmax + context partial (flash-style).
// grid (SPL, BB): block = (split, b). Each thread owns 8 contiguous n.
// 4 timesteps per macro-iter (amortize the 2 block barriers), 1-batch prefetch.
// ---------------------------------------------------------------------------
__global__ __launch_bounds__(256, 1) void k_main(
    const float* __restrict__ enc,
    const float* __restrict__ cov,
    const float* __restrict__ wc,
    const float* __restrict__ v)
{
    __shared__ float scov[CHUNK];
    __shared__ unsigned char smask[CHUNK];
    __shared__ float sred[8][4];
    __shared__ float sbc[4];
    int tid  = threadIdx.x;
    int wid  = tid >> 5, lane = tid & 31;
    int sp = blockIdx.x, b = blockIdx.y;
    int t0   = sp * CHUNK;
    int tEnd = min(TT, t0 + CHUNK);
    int len  = tEnd - t0;                  // 228 or 224, divisible by 4

    for (int i = tid; i < len; i += 256){
        scov[i]  = cov[(t0 + i)*BB + b];
        smask[i] = g_mask8[(t0 + i)*BB + b];
    }
    int n0 = tid * 8;
    const float4* dfp = (const float4*)(g_decfea + b*NN + n0);
    float4 df0 = dfp[0], df1 = dfp[1];
    const float4* wcp = (const float4*)(wc + n0);
    float4 w0 = wcp[0], w1 = wcp[1];
    const float4* vp  = (const float4*)(v + n0);
    float4 v0 = vp[0], v1 = vp[1];

    float m = -INFINITY, Z = 0.f;
    float4 A0 = make_float4(0.f,0.f,0.f,0.f);
    float4 A1 = make_float4(0.f,0.f,0.f,0.f);
    __syncthreads();

    // prefetch batch 0
    float4 c0[4], c1[4];
    #pragma unroll
    for (int i = 0; i < 4; ++i){
        const float4* rp = (const float4*)(enc + ((size_t)(t0+i)*BB + b)*NN + n0);
        c0[i] = rp[0]; c1[i] = rp[1];
    }
    int nb = len >> 2;
    for (int it = 0; it < nb; ++it){
        int tb = t0 + it*4;
        bool havenext = (it + 1 < nb);
        float4 x0[4], x1[4];
        if (havenext){
            #pragma unroll
            for (int i = 0; i < 4; ++i){
                const float4* rp = (const float4*)(enc + ((size_t)(tb+4+i)*BB + b)*NN + n0);
                x0[i] = rp[0]; x1[i] = rp[1];
            }
        }
        // per-thread partial dot for each of 4 timesteps
        float part[4];
        #pragma unroll
        for (int i = 0; i < 4; ++i){
            float cv = scov[it*4 + i];
            float p;
            p  = tanh_acc(fmaf(cv, w0.x, c0[i].x + df0.x)) * v0.x;
            p += tanh_acc(fmaf(cv, w0.y, c0[i].y + df0.y)) * v0.y;
            p += tanh_acc(fmaf(cv, w0.z, c0[i].z + df0.z)) * v0.z;
            p += tanh_acc(fmaf(cv, w0.w, c0[i].w + df0.w)) * v0.w;
            p += tanh_acc(fmaf(cv, w1.x, c1[i].x + df1.x)) * v1.x;
            p += tanh_acc(fmaf(cv, w1.y, c1[i].y + df1.y)) * v1.y;
            p += tanh_acc(fmaf(cv, w1.z, c1[i].z + df1.z)) * v1.z;
            p += tanh_acc(fmaf(cv, w1.w, c1[i].w + df1.w)) * v1.w;
            part[i] = p;
        }
        // warp reduce each of the 4 partials
        #pragma unroll
        for (int i = 0; i < 4; ++i)
            #pragma unroll
            for (int off = 16; off; off >>= 1)
                part[i] += __shfl_xor_sync(0xffffffffu, part[i], off);
        if (lane == 0){
            sred[wid][0] = part[0]; sred[wid][1] = part[1];
            sred[wid][2] = part[2]; sred[wid][3] = part[3];
        }
        __syncthreads();
        if (tid < 32){
            float val = sred[tid >> 2][tid & 3];   // 8 warps x 4 scores = 32 values
            val += __shfl_xor_sync(0xffffffffu, val, 4);
            val += __shfl_xor_sync(0xffffffffu, val, 8);
            val += __shfl_xor_sync(0xffffffffu, val, 16);
            if (tid < 4) sbc[tid] = val;           // lanes 0..3 hold totals
        }
        __syncthreads();
        float s[4];
        #pragma unroll
        for (int i = 0; i < 4; ++i)
            s[i] = smask[it*4 + i] ? -INFINITY : sbc[i];
        if (tid < 4) g_scores[(tb + tid)*BB + b] = s[tid];

        // online softmax update (uniform branch across the block)
        float m2 = m;
        #pragma unroll
        for (int i = 0; i < 4; ++i) m2 = fmaxf(m2, s[i]);
        if (m2 != -INFINITY){
            float sc = __expf(m - m2);             // m==-inf -> 0 (acc is still 0)
            float p0 = __expf(s[0]-m2), p1 = __expf(s[1]-m2);
            float p2 = __expf(s[2]-m2), p3 = __expf(s[3]-m2);
            Z = Z*sc + (p0+p1) + (p2+p3);
            A0.x = fmaf(A0.x, sc, p0*c0[0].x + p1*c0[1].x + p2*c0[2].x + p3*c0[3].x);
            A0.y = fmaf(A0.y, sc, p0*c0[0].y + p1*c0[1].y + p2*c0[2].y + p3*c0[3].y);
            A0.z = fmaf(A0.z, sc, p0*c0[0].z + p1*c0[1].z + p2*c0[2].z + p3*c0[3].z);
            A0.w = fmaf(A0.w, sc, p0*c0[0].w + p1*c0[1].w + p2*c0[2].w + p3*c0[3].w);
            A1.x = fmaf(A1.x, sc, p0*c1[0].x + p1*c1[1].x + p2*c1[2].x + p3*c1[3].x);
            A1.y = fmaf(A1.y, sc, p0*c1[0].y + p1*c1[1].y + p2*c1[2].y + p3*c1[3].y);
            A1.z = fmaf(A1.z, sc, p0*c1[0].z + p1*c1[1].z + p2*c1[2].z + p3*c1[3].z);
            A1.w = fmaf(A1.w, sc, p0*c1[0].w + p1*c1[1].w + p2*c1[2].w + p3*c1[3].w);
            m = m2;
        }
        if (havenext){
            #pragma unroll
            for (int i = 0; i < 4; ++i){ c0[i] = x0[i]; c1[i] = x1[i]; }
        }
    }
    if (tid == 0){
        g_m[b*SPL + sp] = m;
        g_z[b*SPL + sp] = Z;
    }
    float4* op = (float4*)(g_acc + (size_t)(b*SPL + sp)*NN + n0);
    op[0] = A0; op[1] = A1;
}

// ---------------------------------------------------------------------------
// Kernel 3: combine split partials -> c, attn_dist, coverage_out
// grid BB blocks x 256 thr.
// ---------------------------------------------------------------------------
__global__ void k_combine(const float* __restrict__ cov,
                          float* __restrict__ out){
    __shared__ float sw[SPL];
    __shared__ float sM, sInvZ;
    int b = blockIdx.x, tid = threadIdx.x;
    if (tid < 32){
        float mv = (tid < SPL) ? g_m[b*SPL + tid] : -INFINITY;
        float zv = (tid < SPL) ? g_z[b*SPL + tid] : 0.f;
        float M = mv;
        #pragma unroll
        for (int off = 16; off; off >>= 1)
            M = fmaxf(M, __shfl_xor_sync(0xffffffffu, M, off));
        float zz = zv * __expf(mv - M);
        float Zs = zz;
        #pragma unroll
        for (int off = 16; off; off >>= 1)
            Zs += __shfl_xor_sync(0xffffffffu, Zs, off);
        float inv = 1.0f / Zs;
        if (tid < SPL) sw[tid] = __expf(mv - M) * inv;
        if (tid == 0){ sM = M; sInvZ = inv; }
    }
    __syncthreads();
    float M = sM, inv = sInvZ;

    // context c[b, n]
    int n0 = tid * 8;
    float4 r0 = make_float4(0.f,0.f,0.f,0.f);
    float4 r1 = make_float4(0.f,0.f,0.f,0.f);
    #pragma unroll
    for (int s = 0; s < SPL; ++s){
        const float4* p = (const float4*)(g_acc + (size_t)(b*SPL + s)*NN + n0);
        float w = sw[s];
        float4 x = p[0], y = p[1];
        r0.x = fmaf(w, x.x, r0.x); r0.y = fmaf(w, x.y, r0.y);
        r0.z = fmaf(w, x.z, r0.z); r0.w = fmaf(w, x.w, r0.w);
        r1.x = fmaf(w, y.x, r1.x); r1.y = fmaf(w, y.y, r1.y);
        r1.z = fmaf(w, y.z, r1.z); r1.w = fmaf(w, y.w, r1.w);
    }
    float4* co = (float4*)(out + b*NN + n0);
    co[0] = r0; co[1] = r1;

    // attn_dist + coverage_out
    for (int t = tid; t < TT; t += 256){
        float s = g_scores[t*BB + b];
        float a = __expf(s - M) * inv;    // masked: s=-inf -> a=0
        out[BB*NN + t*BB + b] = a;
        out[BB*NN + TT*BB + t*BB + b] = cov[t*BB + b] + a;
    }
}

// ---------------------------------------------------------------------------
extern "C" void kernel_launch(void* const* d_in, const int* in_sizes, int n_in,
                              void* d_out, int out_size){
    const float*         dec  = (const float*)d_in[0];          // [B,H]
    const float*         enc  = (const float*)d_in[1];          // [T,B,N]
    const unsigned char* mask = (const unsigned char*)d_in[2];  // [T,B] bool (dtype detected on device)
    const float*         cov  = (const float*)d_in[3];          // [T,B]
    const float*         Wd   = (const float*)d_in[4];          // [N,H]
    const float*         bd   = (const float*)d_in[5];          // [N]
    const float*         wc   = (const float*)d_in[6];          // [N]
    const float*         v    = (const float*)d_in[7];          // [N]
    float* out = (float*)d_out;  // c[B,N] | attn[T,B] | coverage_out[T,B]

    k_maskconv<<<(TT*BB + 255)/256, 256>>>(mask);
    k_decfea<<<NN/16, 256>>>(dec, Wd, bd);
    k_main<<<dim3(SPL, BB), 256>>>(enc, cov, wc, v);
    k_combine<<<BB, 256>>>(cov, out);
}

// round 3
// speedup vs baseline: 1.2629x; 1.2629x over previous
#include <cuda_runtime.h>
#include <math.h>

#define TT 2048
#define BB 16
#define NN 2048
#define HH 1024
#define SPL 9
#define CHUNK 228   // ceil(2048/9): splits 0..7 = 228 t, split 8 = 224 t (both %4==0)
#define THR 512     // k_main threads (16 warps)

// scratch (device globals: no allocation allowed in kernel_launch)
__device__ float g_decfea[BB*NN];
__device__ float g_scores[TT*BB];
__device__ float g_m[BB*SPL];
__device__ float g_z[BB*SPL];
__device__ float g_acc[BB*SPL*NN];
__device__ unsigned char g_mask8[TT*BB];

// single-MUFU tanh (sm_75+), max err ~5e-4 abs — fine vs 1e-3 threshold
__device__ __forceinline__ float tanhfast(float x){
    float y;
    asm("tanh.approx.f32 %0, %1;" : "=f"(y) : "f"(x));
    return y;
}

// ---------------------------------------------------------------------------
// Kernel 0: normalize padding mask to uint8 regardless of storage dtype.
// Detect from first 32 words (random ~50% mask => misdetect prob ~2^-32).
// ---------------------------------------------------------------------------
__global__ void k_maskconv(const unsigned char* __restrict__ mraw){
    const unsigned int* w = (const unsigned int*)mraw;
    int is_word = 1;   // int32 (0/1) or float32 (0.0/1.0) storage
    #pragma unroll
    for (int i = 0; i < 32; ++i){
        unsigned int x = w[i];
        if (x != 0u && x != 1u && x != 0x3F800000u) is_word = 0;
    }
    int idx = blockIdx.x*256 + threadIdx.x;
    if (idx < TT*BB){
        unsigned char mv = is_word ? (unsigned char)(w[idx] != 0u)
                                   : (unsigned char)(mraw[idx] != 0);
        g_mask8[idx] = mv;
    }
}

// ---------------------------------------------------------------------------
// Kernel 1: dec_fea[b,n] = dot(dec[b,:], Wd[n,:]) + bd[n]
// ---------------------------------------------------------------------------
__global__ void k_decfea(const float* __restrict__ dec,
                         const float* __restrict__ Wd,
                         const float* __restrict__ bd){
    __shared__ float sdec[8*HH];       // 32 KB
    __shared__ float sred[8][256];     // 8 KB
    int tid  = threadIdx.x;
    int wid  = tid >> 5, lane = tid & 31;
    int nbase = blockIdx.x * 16;
    for (int half = 0; half < 2; ++half){
        const float4* dg = (const float4*)(dec + half*8*HH);
        float4* sg = (float4*)sdec;
        #pragma unroll
        for (int i = 0; i < 8; ++i) sg[tid + i*256] = dg[tid + i*256];
        __syncthreads();
        for (int r = 0; r < 16; ++r){
            int n = nbase + r;
            float4 w = ((const float4*)(Wd + (size_t)n*HH))[tid];
            float a[8];
            #pragma unroll
            for (int b = 0; b < 8; ++b){
                float4 d = ((const float4*)(sdec + b*HH))[tid];
                a[b] = w.x*d.x + w.y*d.y + w.z*d.z + w.w*d.w;
            }
            #pragma unroll
            for (int b = 0; b < 8; ++b) sred[b][tid] = a[b];
            __syncthreads();
            float vsum = 0.f;
            #pragma unroll
            for (int k = 0; k < 8; ++k) vsum += sred[wid][lane + 32*k];
            #pragma unroll
            for (int off = 16; off; off >>= 1)
                vsum += __shfl_xor_sync(0xffffffffu, vsum, off);
            if (lane == 0) g_decfea[(half*8 + wid)*NN + n] = vsum + bd[n];
            __syncthreads();
        }
    }
}

// ---------------------------------------------------------------------------
// Kernel 2: fused scores + online softmax + context partial (flash-style).
// grid (SPL, BB); 512 threads; each thread owns 4 contiguous n.
// 4 timesteps/macro-iter; 1-batch register prefetch.
// ---------------------------------------------------------------------------
__global__ __launch_bounds__(THR, 1) void k_main(
    const float* __restrict__ enc,
    const float* __restrict__ cov,
    const float* __restrict__ wc,
    const float* __restrict__ v)
{
    __shared__ float scov[CHUNK];
    __shared__ unsigned char smask[CHUNK];
    __shared__ float sred[16][4];
    __shared__ float sbc[4];
    int tid  = threadIdx.x;
    int wid  = tid >> 5, lane = tid & 31;
    int sp = blockIdx.x, b = blockIdx.y;
    int t0   = sp * CHUNK;
    int tEnd = min(TT, t0 + CHUNK);
    int len  = tEnd - t0;                  // 228 or 224, divisible by 4

    for (int i = tid; i < len; i += THR){
        scov[i]  = cov[(t0 + i)*BB + b];
        smask[i] = g_mask8[(t0 + i)*BB + b];
    }
    int n0 = tid * 4;
    float4 df = *(const float4*)(g_decfea + b*NN + n0);
    float4 w  = *(const float4*)(wc + n0);
    float4 vv = *(const float4*)(v + n0);

    float m = -INFINITY, Z = 0.f;
    float4 A = make_float4(0.f,0.f,0.f,0.f);
    __syncthreads();

    // prefetch batch 0
    float4 c[4];
    #pragma unroll
    for (int i = 0; i < 4; ++i)
        c[i] = *(const float4*)(enc + ((size_t)(t0+i)*BB + b)*NN + n0);

    int nb = len >> 2;
    for (int it = 0; it < nb; ++it){
        int tb = t0 + it*4;
        bool havenext = (it + 1 < nb);
        float4 x[4];
        if (havenext){
            #pragma unroll
            for (int i = 0; i < 4; ++i)
                x[i] = *(const float4*)(enc + ((size_t)(tb+4+i)*BB + b)*NN + n0);
        }
        // per-thread partial dot for each of 4 timesteps
        float part[4];
        #pragma unroll
        for (int i = 0; i < 4; ++i){
            float cv = scov[it*4 + i];
            float p;
            p  = tanhfast(fmaf(cv, w.x, c[i].x + df.x)) * vv.x;
            p += tanhfast(fmaf(cv, w.y, c[i].y + df.y)) * vv.y;
            p += tanhfast(fmaf(cv, w.z, c[i].z + df.z)) * vv.z;
            p += tanhfast(fmaf(cv, w.w, c[i].w + df.w)) * vv.w;
            part[i] = p;
        }
        #pragma unroll
        for (int i = 0; i < 4; ++i)
            #pragma unroll
            for (int off = 16; off; off >>= 1)
                part[i] += __shfl_xor_sync(0xffffffffu, part[i], off);
        if (lane == 0){
            sred[wid][0] = part[0]; sred[wid][1] = part[1];
            sred[wid][2] = part[2]; sred[wid][3] = part[3];
        }
        __syncthreads();
        if (tid < 64){
            int s  = tid >> 4;             // score 0..3
            int ww = tid & 15;             // warp 0..15
            float val = sred[ww][s];
            val += __shfl_xor_sync(0xffffffffu, val, 1);
            val += __shfl_xor_sync(0xffffffffu, val, 2);
            val += __shfl_xor_sync(0xffffffffu, val, 4);
            val += __shfl_xor_sync(0xffffffffu, val, 8);
            if (ww == 0) sbc[s] = val;
        }
        __syncthreads();
        float s[4];
        #pragma unroll
        for (int i = 0; i < 4; ++i)
            s[i] = smask[it*4 + i] ? -INFINITY : sbc[i];
        if (tid < 4) g_scores[(tb + tid)*BB + b] = s[tid];

        // online softmax update (uniform branch across the block)
        float m2 = m;
        #pragma unroll
        for (int i = 0; i < 4; ++i) m2 = fmaxf(m2, s[i]);
        if (m2 != -INFINITY){
            float sc = __expf(m - m2);             // m==-inf -> 0 (A still 0)
            float p0 = __expf(s[0]-m2), p1 = __expf(s[1]-m2);
            float p2 = __expf(s[2]-m2), p3 = __expf(s[3]-m2);
            Z = Z*sc + (p0+p1) + (p2+p3);
            A.x = fmaf(A.x, sc, p0*c[0].x + p1*c[1].x + p2*c[2].x + p3*c[3].x);
            A.y = fmaf(A.y, sc, p0*c[0].y + p1*c[1].y + p2*c[2].y + p3*c[3].y);
            A.z = fmaf(A.z, sc, p0*c[0].z + p1*c[1].z + p2*c[2].z + p3*c[3].z);
            A.w = fmaf(A.w, sc, p0*c[0].w + p1*c[1].w + p2*c[2].w + p3*c[3].w);
            m = m2;
        }
        if (havenext){
            #pragma unroll
            for (int i = 0; i < 4; ++i) c[i] = x[i];
        }
    }
    if (tid == 0){
        g_m[b*SPL + sp] = m;
        g_z[b*SPL + sp] = Z;
    }
    *(float4*)(g_acc + (size_t)(b*SPL + sp)*NN + n0) = A;
}

// ---------------------------------------------------------------------------
// Kernel 3: combine. blocks 0..15: context c[b,:]. blocks 16..47: attn +
// coverage over the flat (t*16+b) index — fully coalesced.
// ---------------------------------------------------------------------------
__global__ void k_combine(const float* __restrict__ cov,
                          float* __restrict__ out){
    int tid = threadIdx.x;
    if (blockIdx.x < BB){
        // ---- context for batch b ----
        int b = blockIdx.x;
        __shared__ float sw[SPL];
        if (tid < 32){
            float mv = (tid < SPL) ? g_m[b*SPL + tid] : -INFINITY;
            float zv = (tid < SPL) ? g_z[b*SPL + tid] : 0.f;
            float M = mv;
            #pragma unroll
            for (int off = 16; off; off >>= 1)
                M = fmaxf(M, __shfl_xor_sync(0xffffffffu, M, off));
            float zz = zv * __expf(mv - M);
            float Zs = zz;
            #pragma unroll
            for (int off = 16; off; off >>= 1)
                Zs += __shfl_xor_sync(0xffffffffu, Zs, off);
            float inv = 1.0f / Zs;
            if (tid < SPL) sw[tid] = __expf(mv - M) * inv;
        }
        __syncthreads();
        int n0 = tid * 8;
        float4 r0 = make_float4(0.f,0.f,0.f,0.f);
        float4 r1 = make_float4(0.f,0.f,0.f,0.f);
        #pragma unroll
        for (int s = 0; s < SPL; ++s){
            const float4* p = (const float4*)(g_acc + (size_t)(b*SPL + s)*NN + n0);
            float wgt = sw[s];
            float4 x = p[0], y = p[1];
            r0.x = fmaf(wgt, x.x, r0.x); r0.y = fmaf(wgt, x.y, r0.y);
            r0.z = fmaf(wgt, x.z, r0.z); r0.w = fmaf(wgt, x.w, r0.w);
            r1.x = fmaf(wgt, y.x, r1.x); r1.y = fmaf(wgt, y.y, r1.y);
            r1.z = fmaf(wgt, y.z, r1.z); r1.w = fmaf(wgt, y.w, r1.w);
        }
        float4* co = (float4*)(out + b*NN + n0);
        co[0] = r0; co[1] = r1;
    } else {
        // ---- attn_dist + coverage_out, flat-indexed (coalesced) ----
        __shared__ float sM[BB], sInv[BB];
        if (tid < BB){
            int b = tid;
            float M = -INFINITY;
            #pragma unroll
            for (int s = 0; s < SPL; ++s) M = fmaxf(M, g_m[b*SPL + s]);
            float Zs = 0.f;
            #pragma unroll
            for (int s = 0; s < SPL; ++s) Zs += g_z[b*SPL + s] * __expf(g_m[b*SPL + s] - M);
            sM[b] = M; sInv[b] = 1.0f / Zs;
        }
        __syncthreads();
        int base = (blockIdx.x - BB) * 256 + tid;   // 32 blocks x 256 thr = 8192
        #pragma unroll
        for (int i = 0; i < 4; ++i){
            int idx = base + i * 8192;              // covers 32768 = TT*BB
            int b = idx & (BB-1);
            float s = g_scores[idx];
            float a = __expf(s - sM[b]) * sInv[b];  // masked: s=-inf -> a=0
            out[BB*NN + idx] = a;
            out[BB*NN + TT*BB + idx] = cov[idx] + a;
        }
    }
}

// ---------------------------------------------------------------------------
extern "C" void kernel_launch(void* const* d_in, const int* in_sizes, int n_in,
                              void* d_out, int out_size){
    const float*         dec  = (const float*)d_in[0];          // [B,H]
    const float*         enc  = (const float*)d_in[1];          // [T,B,N]
    const unsigned char* mask = (const unsigned char*)d_in[2];  // [T,B] (dtype auto-detected)
    const float*         cov  = (const float*)d_in[3];          // [T,B]
    const float*         Wd   = (const float*)d_in[4];          // [N,H]
    const float*         bd   = (const float*)d_in[5];          // [N]
    const float*         wc   = (const float*)d_in[6];          // [N]
    const float*         v    = (const float*)d_in[7];          // [N]
    float* out = (float*)d_out;  // c[B,N] | attn[T,B] | coverage_out[T,B]

    k_maskconv<<<(TT*BB + 255)/256, 256>>>(mask);
    k_decfea<<<NN/16, 256>>>(dec, Wd, bd);
    k_main<<<dim3(SPL, BB), THR>>>(enc, cov, wc, v);
    k_combine<<<BB + 32, 256>>>(cov, out);
}